// round 3
// baseline (speedup 1.0000x reference)
#include <cuda_runtime.h>
#include <math.h>

// ---------------------------------------------------------------------------
// TrLaplacianDP: out = embs + noise, where noise[0:300] are the first 300
// accepted samples of a truncated-Laplacian rejection scan over (sgn, u).
//
// R3: fp32 log on the hot path (double-precision recompute only within a
// 1e-4 boundary band, ~2-3 samples/run), single fused noise kernel, and an
// exact-fit unpredicated streaming add kernel.
// ---------------------------------------------------------------------------

#define EMBS_DIM 300
#define T_N      1024           // noise kernel block size

// Device scratch (no allocations allowed). 304 floats = 75 float4 + pad.
__device__ __align__(16) float g_noise[304];

// ---------------------------------------------------------------------------
// Kernel N: single-block ordered rejection scan, fp32 log hot path.
// ---------------------------------------------------------------------------
__global__ void __launch_bounds__(T_N) noise_kernel(const float* __restrict__ sgn,
                                                    const float* __restrict__ u,
                                                    int n) {
    // Constants from double precision (exact regardless of fast-math).
    const double SCALE_D = 2.0 * 0.005 * sqrt(300.0) / 1.0;
    const float  SCALE_F = (float)SCALE_D;
    const float  A_F     = (float)(-SCALE_D * log(1.0 - 2.0 * 1.0 / sqrt(300.0)));

    __shared__ int s_count;        // accepted before current chunk
    __shared__ int s_warp[32];     // per-warp accept counts
    __shared__ int s_warp_off[33]; // exclusive offsets; [32] = running total

    const int tid  = threadIdx.x;
    const int lane = tid & 31;
    const int wid  = tid >> 5;

    if (tid < 304) g_noise[tid] = 0.0f;
    if (tid == 0) s_count = 0;
    __syncthreads();

    for (int base = 0; base < n; base += T_N) {
        const int idx = base + tid;
        float r = 0.0f;
        bool mask = false;
        if (idx < n) {
            const float sv = sgn[idx];
            const float uv = u[idx];
            const float s  = (sv > 0.0f) ? 1.0f : ((sv < 0.0f) ? -1.0f : 0.0f);
            r = (-SCALE_F * s) * logf(uv);
            // Boundary band: recompute in double so acceptance decisions and
            // stored values match the exact fp32-reference semantics there.
            if (fabsf(fabsf(r) - A_F) < 1e-4f) {
                r = (-SCALE_F * s) * (float)log((double)uv);
            }
            mask = (r >= -A_F) && (r <= A_F);
        }

        // Block-wide ordered exclusive prefix of `mask`.
        const unsigned b = __ballot_sync(0xffffffffu, mask);
        const int wprefix = __popc(b & ((1u << lane) - 1u));
        if (lane == 0) s_warp[wid] = __popc(b);
        __syncthreads();
        if (tid == 0) {
            int acc = s_count;
            #pragma unroll
            for (int w = 0; w < 32; ++w) { s_warp_off[w] = acc; acc += s_warp[w]; }
            s_warp_off[32] = acc;
        }
        __syncthreads();

        if (mask) {
            const int pos = s_warp_off[wid] + wprefix;
            if (pos < EMBS_DIM) g_noise[pos] = r;
        }
        if (tid == 0) s_count = s_warp_off[32];
        __syncthreads();

        if (s_warp_off[32] >= EMBS_DIM) break;   // uniform across the block
    }
}

// ---------------------------------------------------------------------------
// Kernel B (exact fit): out = embs + broadcast(noise).
// Preconditions (checked on host): n == n4*4, n4 == GRID*256*8,
// (GRID*256) % 75 == 0. No predicates, no tail; 8 independent LDG.128.
// ---------------------------------------------------------------------------
#define ADD_GRID  4800
#define ADD_BLK   256
#define ADD_IT    8
#define ADD_STRIDE (ADD_GRID * ADD_BLK)

__global__ void __launch_bounds__(ADD_BLK) add_exact_kernel(
        const float* __restrict__ embs, float* __restrict__ out) {
    __shared__ float4 s_noise[75];
    if (threadIdx.x < 75)
        s_noise[threadIdx.x] = reinterpret_cast<const float4*>(g_noise)[threadIdx.x];
    __syncthreads();

    const float4* __restrict__ in4  = reinterpret_cast<const float4*>(embs);
    float4* __restrict__       out4 = reinterpret_cast<float4*>(out);

    const int v0    = blockIdx.x * ADD_BLK + threadIdx.x;
    const float4 nz = s_noise[v0 % 75];     // stride % 75 == 0 -> invariant

    #pragma unroll
    for (int k = 0; k < ADD_IT; ++k) {
        const int vi = v0 + k * ADD_STRIDE;
        float4 e = __ldcs(&in4[vi]);
        e.x += nz.x; e.y += nz.y; e.z += nz.z; e.w += nz.w;
        __stcs(&out4[vi], e);
    }
}

// ---------------------------------------------------------------------------
// Kernel B (general fallback): any shape.
// ---------------------------------------------------------------------------
__global__ void __launch_bounds__(256) add_general_kernel(
        const float* __restrict__ embs, float* __restrict__ out,
        int n4, int n) {
    __shared__ float4 s_noise[75];
    if (threadIdx.x < 75)
        s_noise[threadIdx.x] = reinterpret_cast<const float4*>(g_noise)[threadIdx.x];
    __syncthreads();

    const float4* __restrict__ in4  = reinterpret_cast<const float4*>(embs);
    float4* __restrict__       out4 = reinterpret_cast<float4*>(out);

    const int stride = gridDim.x * blockDim.x;       // multiple of 75
    const int v0     = blockIdx.x * blockDim.x + threadIdx.x;
    const float4 nz  = s_noise[v0 % 75];

    for (int v = v0; v < n4; v += 8 * stride) {
        #pragma unroll
        for (int k = 0; k < 8; ++k) {
            const int vi = v + k * stride;
            if (vi < n4) {
                float4 e = __ldcs(&in4[vi]);
                e.x += nz.x; e.y += nz.y; e.z += nz.z; e.w += nz.w;
                __stcs(&out4[vi], e);
            }
        }
    }

    const int tail_start = n4 * 4;
    for (int i = tail_start + v0; i < n; i += stride)
        out[i] = embs[i] + g_noise[i % EMBS_DIM];
}

// ---------------------------------------------------------------------------
extern "C" void kernel_launch(void* const* d_in, const int* in_sizes, int n_in,
                              void* d_out, int out_size) {
    const float* embs = (const float*)d_in[0];
    const float* sgn  = (const float*)d_in[1];
    const float* u    = (const float*)d_in[2];
    float* out        = (float*)d_out;

    const int nsamp = in_sizes[1];
    noise_kernel<<<1, T_N>>>(sgn, u, nsamp);

    const int n  = out_size;
    const int n4 = n / 4;
    if (n == n4 * 4 && n4 == ADD_GRID * ADD_BLK * ADD_IT) {
        add_exact_kernel<<<ADD_GRID, ADD_BLK>>>(embs, out);
    } else {
        int grid = (n4 + 256 * 8 - 1) / (256 * 8);
        grid = ((grid + 74) / 75) * 75;              // stride % 75 == 0
        if (grid < 75) grid = 75;
        add_general_kernel<<<grid, 256>>>(embs, out, n4, n);
    }
}